// round 1
// baseline (speedup 1.0000x reference)
#include <cuda_runtime.h>
#include <math.h>

// Problem dims (fixed by setup_inputs)
constexpr int NB = 128, NA = 2, NH = 128, NW = 128;
constexpr int PLANE = NH * NW;            // 16384
constexpr float THRESH = 0.6f;
constexpr float OBJ_SCALE = 5.0f;

// Scratch (no allocation allowed)
__device__ float4 g_box[NB];      // gt_x, gt_y, gt_w, gt_h (grid units)
__device__ int    g_excl[NB];     // best_a*PLANE + gyi*NW + gxi (excluded cell)
__device__ float  g_sel_loss;     // loss_x+y+w+h + OBJ_SCALE*mean((conf_s-1)^2)
__device__ double g_conf2;        // sum of conf^2 over noobj cells
__device__ double g_cnt;          // noobj count

__device__ __forceinline__ float sigf(float x) { return 1.0f / (1.0f + expf(-x)); }

// ---------------------------------------------------------------------------
// Kernel 1: per-batch precompute + selected-cell losses (1 block, 128 threads)
// ---------------------------------------------------------------------------
__global__ void k_setup(const float* __restrict__ out,
                        const float* __restrict__ tgt,
                        const float* __restrict__ anc) {
    int b = threadIdx.x;
    if (b == 0) { g_conf2 = 0.0; g_cnt = 0.0; }

    float t0 = tgt[b*4+0], t1 = tgt[b*4+1], t2 = tgt[b*4+2], t3 = tgt[b*4+3];
    float gx = t0 * (float)NW, gy = t1 * (float)NH;
    float gw = t2 * (float)NW, gh = t3 * (float)NH;

    float a0w = anc[0], a0h = anc[1], a1w = anc[2], a1h = anc[3];
    float ga  = gw * gh;
    float i0 = fminf(gw, a0w) * fminf(gh, a0h);
    float u0 = ga + 1e-16f + a0w * a0h - i0;
    float i1 = fminf(gw, a1w) * fminf(gh, a1h);
    float u1 = ga + 1e-16f + a1w * a1h - i1;
    int best = (i1 / u1) > (i0 / u0) ? 1 : 0;   // argmax, first on tie

    int gxi = (int)gx, gyi = (int)gy;           // positive -> trunc == astype(int32)
    g_box[b]  = make_float4(gx, gy, gw, gh);
    g_excl[b] = best * PLANE + gyi * NW + gxi;

    // Selected-cell predictions
    const float* p = out + ((size_t)(b * NA * 5 + best * 5)) * PLANE + gyi * NW + gxi;
    float xs = sigf(p[0]);
    float ys = sigf(p[PLANE]);
    float ws = p[2 * PLANE];
    float hs = p[3 * PLANE];
    float cs = sigf(p[4 * PLANE]);

    float txv = gx - floorf(gx);
    float tyv = gy - floorf(gy);
    float aw  = best ? a1w : a0w;
    float ah  = best ? a1h : a0h;
    float twv = logf(gw / aw + 1e-16f);
    float thv = logf(gh / ah + 1e-16f);
    float sc  = 2.0f - t2 * t3;

    float dx = (xs - txv) * sc, dy = (ys - tyv) * sc;
    float dw = (ws - twv) * sc, dh = (hs - thv) * sc;
    float l  = dx*dx + dy*dy + dw*dw + dh*dh
             + OBJ_SCALE * (cs - 1.0f) * (cs - 1.0f);

    __shared__ float sh[128];
    sh[b] = l;
    __syncthreads();
    #pragma unroll
    for (int s = 64; s > 0; s >>= 1) {
        if (b < s) sh[b] += sh[b + s];
        __syncthreads();
    }
    if (b == 0) g_sel_loss = sh[0] / (float)NB;
}

// ---------------------------------------------------------------------------
// Kernel 2: streaming IoU + noobj conf^2 reduction (4.19M cells, 4 per thread)
// ---------------------------------------------------------------------------
__global__ void __launch_bounds__(256) k_main(const float* __restrict__ out,
                                              const float* __restrict__ anc) {
    int tid = blockIdx.x * blockDim.x + threadIdx.x;   // 0 .. 1048575
    int i4 = (tid & 31) * 4;        // column start (4 consecutive cols)
    int r  = tid >> 5;
    int j  = r & 127; r >>= 7;      // row
    int a  = r & 1;                 // anchor
    int b  = r >> 1;                // batch

    float4 box  = g_box[b];
    int    excl = g_excl[b];
    float  aw = anc[a * 2], ah = anc[a * 2 + 1];

    size_t base = ((size_t)(b * 10 + a * 5) * NH + j) * NW + i4;
    float4 vx = *(const float4*)(out + base);
    float4 vy = *(const float4*)(out + base + 1 * (size_t)PLANE);
    float4 vw = *(const float4*)(out + base + 2 * (size_t)PLANE);
    float4 vh = *(const float4*)(out + base + 3 * (size_t)PLANE);
    float4 vc = *(const float4*)(out + base + 4 * (size_t)PLANE);

    float gxm = box.x - box.z * 0.5f, gxM = box.x + box.z * 0.5f;
    float gym = box.y - box.w * 0.5f, gyM = box.y + box.w * 0.5f;
    float garea = box.z * box.w;
    int   lbase = a * PLANE + j * NW + i4;

    double conf2 = 0.0;
    int cnt = 0;
    const float* px4 = &vx.x; const float* py4 = &vy.x;
    const float* pw4 = &vw.x; const float* ph4 = &vh.x;
    const float* pc4 = &vc.x;
    #pragma unroll
    for (int k = 0; k < 4; k++) {
        float px = sigf(px4[k]) + (float)(i4 + k);
        float py = sigf(py4[k]) + (float)j;
        float pw = expf(pw4[k]) * aw;
        float ph = expf(ph4[k]) * ah;
        float mx = fminf(px - pw * 0.5f, gxm);
        float Mx = fmaxf(px + pw * 0.5f, gxM);
        float my = fminf(py - ph * 0.5f, gym);
        float My = fmaxf(py + ph * 0.5f, gyM);
        float cw = pw + box.z - (Mx - mx);
        float ch = ph + box.w - (My - my);
        float carea = cw * ch;
        float uarea = pw * ph + garea - carea;
        float iou = (cw <= 0.0f || ch <= 0.0f) ? 0.0f : carea / uarea;
        bool noobj = (iou <= THRESH) && ((lbase + k) != excl);
        if (noobj) {
            float c = sigf(pc4[k]);
            conf2 += (double)(c * c);
            cnt++;
        }
    }

    // warp reduce
    #pragma unroll
    for (int o = 16; o > 0; o >>= 1) {
        conf2 += __shfl_down_sync(0xffffffffu, conf2, o);
        cnt   += __shfl_down_sync(0xffffffffu, cnt, o);
    }
    __shared__ double s_c2[8];
    __shared__ int    s_ct[8];
    int lane = threadIdx.x & 31, wrp = threadIdx.x >> 5;
    if (lane == 0) { s_c2[wrp] = conf2; s_ct[wrp] = cnt; }
    __syncthreads();
    if (wrp == 0) {
        double c2 = (lane < 8) ? s_c2[lane] : 0.0;
        int    ct = (lane < 8) ? s_ct[lane] : 0;
        #pragma unroll
        for (int o = 4; o > 0; o >>= 1) {
            c2 += __shfl_down_sync(0xffffffffu, c2, o);
            ct += __shfl_down_sync(0xffffffffu, ct, o);
        }
        if (lane == 0) {
            atomicAdd(&g_conf2, c2);
            atomicAdd(&g_cnt, (double)ct);
        }
    }
}

// ---------------------------------------------------------------------------
// Kernel 3: finalize scalar
// ---------------------------------------------------------------------------
__global__ void k_final(float* __restrict__ outp) {
    outp[0] = g_sel_loss + (float)(g_conf2 / g_cnt);
}

extern "C" void kernel_launch(void* const* d_in, const int* in_sizes, int n_in,
                              void* d_out, int out_size) {
    const float* out = (const float*)d_in[0];   // (128, 10, 128, 128)
    const float* tgt = (const float*)d_in[1];   // (128, 4)
    const float* anc = (const float*)d_in[2];   // (2, 2)
    float* res = (float*)d_out;

    k_setup<<<1, 128>>>(out, tgt, anc);
    // 128*2*128*128 cells / 4 per thread = 1,048,576 threads
    k_main<<<4096, 256>>>(out, anc);
    k_final<<<1, 1>>>(res);
}

// round 2
// speedup vs baseline: 1.6297x; 1.6297x over previous
#include <cuda_runtime.h>
#include <math.h>

constexpr int NB = 128, NA = 2, NH = 128, NW = 128;
constexpr int PLANE = NH * NW;
constexpr float THRESH = 0.6f;
constexpr float OBJ_SCALE = 5.0f;
constexpr float LN_MARGIN = 0.55961579f;   // ln(1.75) > ln(5/3): safety margin

// Scratch (no allocation allowed)
__device__ float4 g_box[NB];         // gx, gy, gw, gh (grid units)
__device__ float2 g_bnd[NB][NA];     // (lo, hi) screen bounds on w+h
__device__ int    g_excl[NB];        // a*PLANE + gyi*NW + gxi
__device__ float4 g_tc[NB];          // tx, ty, tw, th
__device__ float  g_scl[NB];         // scale = 2 - t2*t3
__device__ float  g_sel;             // coord + obj-conf loss (already /NB)
__device__ double g_conf2;           // sum conf^2 over noobj cells
__device__ unsigned long long g_cnt; // noobj count

__device__ __forceinline__ float sig_precise(float x) { return 1.0f / (1.0f + expf(-x)); }

// ---------------------------------------------------------------------------
// k_init: zero accumulators + per-batch constants (target/anchors only: fast)
// ---------------------------------------------------------------------------
__global__ void k_init(const float* __restrict__ tgt, const float* __restrict__ anc) {
    int b = threadIdx.x;
    if (b == 0) { g_conf2 = 0.0; g_cnt = 0ull; g_sel = 0.0f; }
    if (b >= NB) return;

    float t0 = tgt[b*4+0], t1 = tgt[b*4+1], t2 = tgt[b*4+2], t3 = tgt[b*4+3];
    float gx = t0 * (float)NW, gy = t1 * (float)NH;
    float gw = t2 * (float)NW, gh = t3 * (float)NH;
    float a0w = anc[0], a0h = anc[1], a1w = anc[2], a1h = anc[3];

    float ga = gw * gh;
    float i0 = fminf(gw, a0w) * fminf(gh, a0h);
    float u0 = ga + 1e-16f + a0w * a0h - i0;
    float i1 = fminf(gw, a1w) * fminf(gh, a1h);
    float u1 = ga + 1e-16f + a1w * a1h - i1;
    int best = (i1 / u1) > (i0 / u0) ? 1 : 0;

    int gxi = (int)gx, gyi = (int)gy;
    g_box[b]  = make_float4(gx, gy, gw, gh);
    g_excl[b] = best * PLANE + gyi * NW + gxi;

    float c0 = logf(ga / (a0w * a0h));
    float c1 = logf(ga / (a1w * a1h));
    g_bnd[b][0] = make_float2(c0 - LN_MARGIN, c0 + LN_MARGIN);
    g_bnd[b][1] = make_float2(c1 - LN_MARGIN, c1 + LN_MARGIN);

    float aw = best ? a1w : a0w;
    float ah = best ? a1h : a0h;
    g_tc[b]  = make_float4(gx - floorf(gx), gy - floorf(gy),
                           logf(gw / aw + 1e-16f), logf(gh / ah + 1e-16f));
    g_scl[b] = 2.0f - t2 * t3;
}

// ---------------------------------------------------------------------------
// k_main: streaming pass. Screen on w+h guarantees noobj for ~98% of cells,
// skipping x/y loads and all IoU math there.
// ---------------------------------------------------------------------------
__global__ void __launch_bounds__(256) k_main(const float* __restrict__ out,
                                              const float* __restrict__ anc) {
    int tid = blockIdx.x * blockDim.x + threadIdx.x;
    int i4 = (tid & 31) * 4;
    int r  = tid >> 5;
    int j  = r & 127; r >>= 7;
    int a  = r & 1;
    int b  = r >> 1;

    size_t base = ((size_t)(b * 10 + a * 5) * NH + j) * NW + i4;
    float4 vw = *(const float4*)(out + base + 2 * (size_t)PLANE);
    float4 vh = *(const float4*)(out + base + 3 * (size_t)PLANE);
    float4 vc = *(const float4*)(out + base + 4 * (size_t)PLANE);

    float2 bnd  = g_bnd[b][a];
    int    excl = g_excl[b];
    int    lbase = a * PLANE + j * NW + i4;

    const float* pw4 = &vw.x;
    const float* ph4 = &vh.x;
    const float* pc4 = &vc.x;

    bool pass[4];
    #pragma unroll
    for (int k = 0; k < 4; k++) {
        float s = pw4[k] + ph4[k];
        pass[k] = (s > bnd.x) && (s < bnd.y);
    }
    bool own_excl = (excl >= lbase) && (excl < lbase + 4);
    bool noobj[4] = {true, true, true, true};

    if (pass[0] | pass[1] | pass[2] | pass[3] | own_excl) {
        // Slow path: need x/y planes for IoU (and/or selected-cell loss)
        float4 vx = *(const float4*)(out + base);
        float4 vy = *(const float4*)(out + base + 1 * (size_t)PLANE);
        const float* px4 = &vx.x;
        const float* py4 = &vy.x;

        float4 box = g_box[b];
        float aw = anc[a * 2], ah = anc[a * 2 + 1];
        float gxm = box.x - box.z * 0.5f, gxM = box.x + box.z * 0.5f;
        float gym = box.y - box.w * 0.5f, gyM = box.y + box.w * 0.5f;
        float garea = box.z * box.w;

        #pragma unroll
        for (int k = 0; k < 4; k++) {
            if (pass[k]) {
                float px = sig_precise(px4[k]) + (float)(i4 + k);
                float py = sig_precise(py4[k]) + (float)j;
                float pw = expf(pw4[k]) * aw;
                float ph = expf(ph4[k]) * ah;
                float mx = fminf(px - pw * 0.5f, gxm);
                float Mx = fmaxf(px + pw * 0.5f, gxM);
                float my = fminf(py - ph * 0.5f, gym);
                float My = fmaxf(py + ph * 0.5f, gyM);
                float cw = pw + box.z - (Mx - mx);
                float ch = ph + box.w - (My - my);
                float carea = cw * ch;
                float uarea = pw * ph + garea - carea;
                // iou <= 0.6  <=>  carea <= 0.6*uarea  (uarea > 0)
                noobj[k] = (cw <= 0.0f) || (ch <= 0.0f) || (carea <= THRESH * uarea);
            }
        }
        if (own_excl) {
            int k = excl - lbase;
            noobj[k] = false;  // excluded from noobj sum regardless
            // Selected-cell loss (one thread per batch reaches here)
            float4 tc = g_tc[b];
            float  sc = g_scl[b];
            float xs = sig_precise(px4[k]);
            float ys = sig_precise(py4[k]);
            float ws = pw4[k];
            float hs = ph4[k];
            float cs = sig_precise(pc4[k]);
            float dx = (xs - tc.x) * sc, dy = (ys - tc.y) * sc;
            float dw = (ws - tc.z) * sc, dh = (hs - tc.w) * sc;
            float l  = dx*dx + dy*dy + dw*dw + dh*dh
                     + OBJ_SCALE * (cs - 1.0f) * (cs - 1.0f);
            atomicAdd(&g_sel, l * (1.0f / (float)NB));
        }
    }

    float conf2f = 0.0f;
    int cnt = 0;
    #pragma unroll
    for (int k = 0; k < 4; k++) {
        if (noobj[k]) {
            float t  = 1.0f + __expf(-pc4[k]);
            float rr = __fdividef(1.0f, t);
            conf2f += rr * rr;
            cnt++;
        }
    }

    // warp reduce (float partial -> double at warp leader)
    #pragma unroll
    for (int o = 16; o > 0; o >>= 1) {
        conf2f += __shfl_down_sync(0xffffffffu, conf2f, o);
        cnt    += __shfl_down_sync(0xffffffffu, cnt, o);
    }
    __shared__ double s_c2[8];
    __shared__ int    s_ct[8];
    int lane = threadIdx.x & 31, wrp = threadIdx.x >> 5;
    if (lane == 0) { s_c2[wrp] = (double)conf2f; s_ct[wrp] = cnt; }
    __syncthreads();
    if (wrp == 0) {
        double c2 = (lane < 8) ? s_c2[lane] : 0.0;
        int    ct = (lane < 8) ? s_ct[lane] : 0;
        #pragma unroll
        for (int o = 4; o > 0; o >>= 1) {
            c2 += __shfl_down_sync(0xffffffffu, c2, o);
            ct += __shfl_down_sync(0xffffffffu, ct, o);
        }
        if (lane == 0) {
            atomicAdd(&g_conf2, c2);
            atomicAdd(&g_cnt, (unsigned long long)ct);
        }
    }
}

// ---------------------------------------------------------------------------
__global__ void k_final(float* __restrict__ outp) {
    outp[0] = g_sel + (float)(g_conf2 / (double)g_cnt);
}

extern "C" void kernel_launch(void* const* d_in, const int* in_sizes, int n_in,
                              void* d_out, int out_size) {
    const float* out = (const float*)d_in[0];   // (128, 10, 128, 128)
    const float* tgt = (const float*)d_in[1];   // (128, 4)
    const float* anc = (const float*)d_in[2];   // (2, 2)
    float* res = (float*)d_out;

    k_init<<<1, 128>>>(tgt, anc);
    k_main<<<4096, 256>>>(out, anc);
    k_final<<<1, 1>>>(res);
}